// round 9
// baseline (speedup 1.0000x reference)
#include <cuda_runtime.h>
#include <cuda.h>

// Correlation / cost-volume layer: kernel_size=1, stride=1, max_disp=4.
// out[b, d, y, x] = (1/C) * sum_c in1[b,c,y,x] * in2[b,c, y+dy-4, x+dx-4]
// d = dy*9 + dx, dy,dx in [0,9). Fixed shapes: B=8, C=192, H=W=128.
//
// P=4 pixels x G=3 dy-rows per thread, FMA2 paired over dx (parity phase so
// every b-pair aliases an LDS.128 quad). TH=4 tile, 96 threads, occupancy 4.
// 3-stage TMA ring: each load has ~2 chunk-compute times to land, so the
// full-barrier wait always takes the fast path.

#define MAXD 4
#define WIN  9
#define NDISP 81

#define BB 8
#define CC 192
#define HH 128
#define WW 128

#define TH 4            // tile rows per CTA
#define TW 32           // tile cols per CTA
#define KC 6            // channels per chunk (32 chunks)
#define NCHUNK (CC / KC)
#define NSTAGE 3
#define NTHREADS 96     // 3 dy-groups (== warps) * (4 ty * 8 tx)

#define S2H (TH + 8)    // 12
#define S2W (TW + 8)    // 40
#define S1BYTES (KC * TH * TW * 4)       // 3072
#define S2BYTES (KC * S2H * S2W * 4)     // 11520
#define CHUNK_BYTES (S1BYTES + S2BYTES)  // 14592

// packed f32x2 ops
#define FMA2(d, a, b)      asm("fma.rn.f32x2 %0, %1, %2, %0;" : "+l"(d) : "l"(a), "l"(b))
#define PACK2(d, lo, hi)   asm("mov.b64 %0, {%1, %2};" : "=l"(d) : "f"(lo), "f"(hi))
#define UNPACK2(lo, hi, v) asm("mov.b64 {%0, %1}, %2;" : "=f"(lo), "=f"(hi) : "l"(v))

__device__ __forceinline__ unsigned smem_u32(const void* p) {
    unsigned a;
    asm("{ .reg .u64 t; cvta.to.shared.u64 t, %1; cvt.u32.u64 %0, t; }"
        : "=r"(a) : "l"(p));
    return a;
}
__device__ __forceinline__ void mbar_init(unsigned mbar, unsigned count) {
    asm volatile("mbarrier.init.shared.b64 [%0], %1;" :: "r"(mbar), "r"(count) : "memory");
}
__device__ __forceinline__ void mbar_expect_tx(unsigned mbar, unsigned bytes) {
    asm volatile("mbarrier.arrive.expect_tx.shared.b64 _, [%0], %1;"
                 :: "r"(mbar), "r"(bytes) : "memory");
}
__device__ __forceinline__ void mbar_wait(unsigned mbar, unsigned parity) {
    asm volatile(
        "{\n\t"
        ".reg .pred P;\n\t"
        "WAIT_LOOP_%=:\n\t"
        "mbarrier.try_wait.parity.acquire.cta.shared::cta.b64 P, [%0], %1, 0x989680;\n\t"
        "@P bra.uni WAIT_DONE_%=;\n\t"
        "bra.uni WAIT_LOOP_%=;\n\t"
        "WAIT_DONE_%=:\n\t"
        "}"
        :: "r"(mbar), "r"(parity) : "memory");
}
__device__ __forceinline__ void tma_load_3d(unsigned smem_dst, const void* tmap,
                                            int cx, int cy, int cz, unsigned mbar) {
    asm volatile(
        "cp.async.bulk.tensor.3d.shared::cta.global.tile.mbarrier::complete_tx::bytes "
        "[%0], [%1, {%2, %3, %4}], [%5];"
        :: "r"(smem_dst), "l"(tmap), "r"(cx), "r"(cy), "r"(cz), "r"(mbar)
        : "memory");
}

__global__ __launch_bounds__(NTHREADS, 4)
void corr_kernel(const __grid_constant__ CUtensorMap t1map,
                 const __grid_constant__ CUtensorMap t2map,
                 float* __restrict__ out)
{
    __shared__ __align__(128) float s1[NSTAGE][KC][TH][TW];      // 9 KB
    __shared__ __align__(128) float s2[NSTAGE][KC][S2H][S2W];    // 33.75 KB
    __shared__ __align__(8) unsigned long long mbar_full[NSTAGE];

    const int tx0 = blockIdx.x * TW;
    const int ty0 = blockIdx.y * TH;
    const int b   = blockIdx.z;

    const int tid   = threadIdx.x;
    const int group = tid >> 5;        // warp id == dy group: dy in [3g, 3g+3)
    const int lane  = tid & 31;
    const int tx    = lane & 7;        // x-quad index
    const int ty    = lane >> 3;       // 0..3
    const int dyb   = group * 3;

    unsigned mbA[NSTAGE], s1A[NSTAGE], s2A[NSTAGE];
    #pragma unroll
    for (int s = 0; s < NSTAGE; ++s) {
        mbA[s] = smem_u32(&mbar_full[s]);
        s1A[s] = smem_u32(&s1[s][0][0][0]);
        s2A[s] = smem_u32(&s2[s][0][0][0]);
    }
    const int zbase = b * CC;

    if (tid == 0) {
        #pragma unroll
        for (int s = 0; s < NSTAGE; ++s) mbar_init(mbA[s], 1);
    }
    __syncthreads();

    if (tid == 0) {
        #pragma unroll
        for (int s = 0; s < NSTAGE; ++s) {
            mbar_expect_tx(mbA[s], CHUNK_BYTES);
            tma_load_3d(s1A[s], &t1map, tx0, ty0, zbase + s * KC, mbA[s]);
            tma_load_3d(s2A[s], &t2map, tx0 - MAXD, ty0 - MAXD, zbase + s * KC, mbA[s]);
        }
    }

    // accumulators: per (g, px): 4 dx-pairs (phase by px parity) + 1 scalar.
    // p even: pairs (0,1)(2,3)(4,5)(6,7), scalar dx=8
    // p odd : scalar dx=0, pairs (1,2)(3,4)(5,6)(7,8)
    unsigned long long acc2[3][4][4];   // 96 regs
    float accS[3][4];                   // 12 regs
    #pragma unroll
    for (int g = 0; g < 3; ++g)
        #pragma unroll
        for (int p = 0; p < 4; ++p) {
            accS[g][p] = 0.0f;
            #pragma unroll
            for (int j = 0; j < 4; ++j)
                acc2[g][p][j] = 0ull;
        }

    int slot = 0;
    unsigned par = 0;
    for (int k = 0; k < NCHUNK; ++k) {
        mbar_wait(mbA[slot], par);
        const int buf = slot;

        // ---- compute chunk k from buf ----
        #pragma unroll
        for (int kc = 0; kc < KC; ++kc) {
            // hoist all 10 LDS.128 of this kc before the FMA block (MLP ~10)
            float4 a4 = *(const float4*)&s1[buf][kc][ty][tx * 4];
            float4 w[3][3];
            #pragma unroll
            for (int g = 0; g < 3; ++g) {
                const float* rowp = &s2[buf][kc][ty + dyb + g][tx * 4];
                w[g][0] = *(const float4*)(rowp);
                w[g][1] = *(const float4*)(rowp + 4);
                w[g][2] = *(const float4*)(rowp + 8);
            }

            float af[4] = {a4.x, a4.y, a4.z, a4.w};
            unsigned long long aB[4];
            PACK2(aB[0], a4.x, a4.x);
            PACK2(aB[1], a4.y, a4.y);
            PACK2(aB[2], a4.z, a4.z);
            PACK2(aB[3], a4.w, a4.w);

            #pragma unroll
            for (int g = 0; g < 3; ++g) {
                float4 q0 = w[g][0], q1 = w[g][1], q2 = w[g][2];
                // even-aligned window pairs: sub-pairs of the quads (elided)
                unsigned long long e[6];
                PACK2(e[0], q0.x, q0.y); PACK2(e[1], q0.z, q0.w);
                PACK2(e[2], q1.x, q1.y); PACK2(e[3], q1.z, q1.w);
                PACK2(e[4], q2.x, q2.y); PACK2(e[5], q2.z, q2.w);
                float wf[12] = {q0.x, q0.y, q0.z, q0.w,
                                q1.x, q1.y, q1.z, q1.w,
                                q2.x, q2.y, q2.z, q2.w};

                #pragma unroll
                for (int p = 0; p < 4; ++p) {
                    const int off = (p + 1) >> 1;   // 0,1,1,2
                    #pragma unroll
                    for (int j = 0; j < 4; ++j)
                        FMA2(acc2[g][p][j], aB[p], e[off + j]);
                    const int sw = (p & 1) ? p : (p + 8);
                    accS[g][p] = fmaf(af[p], wf[sw], accS[g][p]);
                }
            }
        }
        __syncthreads();

        // refill this slot with chunk k+NSTAGE
        if (k + NSTAGE < NCHUNK && tid == 0) {
            mbar_expect_tx(mbA[slot], CHUNK_BYTES);
            tma_load_3d(s1A[slot], &t1map, tx0, ty0, zbase + (k + NSTAGE) * KC, mbA[slot]);
            tma_load_3d(s2A[slot], &t2map, tx0 - MAXD, ty0 - MAXD, zbase + (k + NSTAGE) * KC, mbA[slot]);
        }
        if (++slot == NSTAGE) { slot = 0; par ^= 1; }
    }

    // ---- epilogue: unpack dx-pairs, scale by 1/C, float4 stores ----
    const float scale = 1.0f / (float)CC;
    const int y  = ty0 + ty;
    const int x0 = tx0 + tx * 4;
    #pragma unroll
    for (int g = 0; g < 3; ++g) {
        float v[WIN][4];
        #pragma unroll
        for (int p = 0; p < 4; ++p) {
            if ((p & 1) == 0) {
                #pragma unroll
                for (int j = 0; j < 4; ++j)
                    UNPACK2(v[2 * j][p], v[2 * j + 1][p], acc2[g][p][j]);
                v[8][p] = accS[g][p];
            } else {
                v[0][p] = accS[g][p];
                #pragma unroll
                for (int j = 0; j < 4; ++j)
                    UNPACK2(v[2 * j + 1][p], v[2 * j + 2][p], acc2[g][p][j]);
            }
        }
        #pragma unroll
        for (int dx = 0; dx < WIN; ++dx) {
            int d = (dyb + g) * WIN + dx;
            *(float4*)&out[(((long)(b * NDISP) + d) * HH + y) * WW + x0] =
                make_float4(v[dx][0] * scale, v[dx][1] * scale,
                            v[dx][2] * scale, v[dx][3] * scale);
        }
    }
}

typedef CUresult (*EncodeFn)(CUtensorMap*, CUtensorMapDataType, cuuint32_t, void*,
                             const cuuint64_t*, const cuuint64_t*, const cuuint32_t*,
                             const cuuint32_t*, CUtensorMapInterleave, CUtensorMapSwizzle,
                             CUtensorMapL2promotion, CUtensorMapFloatOOBfill);

extern "C" void kernel_launch(void* const* d_in, const int* in_sizes, int n_in,
                              void* d_out, int out_size)
{
    float* in1 = (float*)d_in[0];
    float* in2 = (float*)d_in[1];
    float* out = (float*)d_out;

    EncodeFn encode = nullptr;
    cudaDriverEntryPointQueryResult qr;
    cudaGetDriverEntryPoint("cuTensorMapEncodeTiled", (void**)&encode,
                            cudaEnableDefault, &qr);

    CUtensorMap t1map, t2map;
    cuuint64_t dims[3]    = { WW, HH, (cuuint64_t)(BB * CC) };
    cuuint64_t strides[2] = { WW * 4ull, (cuuint64_t)HH * WW * 4ull };
    cuuint32_t elemstr[3] = { 1, 1, 1 };

    cuuint32_t box1[3] = { TW, TH, KC };
    encode(&t1map, CU_TENSOR_MAP_DATA_TYPE_FLOAT32, 3, in1,
           dims, strides, box1, elemstr,
           CU_TENSOR_MAP_INTERLEAVE_NONE, CU_TENSOR_MAP_SWIZZLE_NONE,
           CU_TENSOR_MAP_L2_PROMOTION_L2_128B, CU_TENSOR_MAP_FLOAT_OOB_FILL_NONE);

    cuuint32_t box2[3] = { S2W, S2H, KC };
    encode(&t2map, CU_TENSOR_MAP_DATA_TYPE_FLOAT32, 3, in2,
           dims, strides, box2, elemstr,
           CU_TENSOR_MAP_INTERLEAVE_NONE, CU_TENSOR_MAP_SWIZZLE_NONE,
           CU_TENSOR_MAP_L2_PROMOTION_L2_128B, CU_TENSOR_MAP_FLOAT_OOB_FILL_NONE);

    dim3 grid(WW / TW, HH / TH, BB);   // (4, 32, 8) = 1024 CTAs
    dim3 block(NTHREADS);
    corr_kernel<<<grid, block>>>(t1map, t2map, out);
}

// round 10
// speedup vs baseline: 1.0995x; 1.0995x over previous
#include <cuda_runtime.h>
#include <cuda.h>

// Correlation / cost-volume layer: kernel_size=1, stride=1, max_disp=4.
// out[b, d, y, x] = (1/C) * sum_c in1[b,c,y,x] * in2[b,c, y+dy-4, x+dx-4]
// d = dy*9 + dx, dy,dx in [0,9). Fixed shapes: B=8, C=192, H=W=128.
//
// R8 compute body (P=4 pixels x G=3 dy-rows, FMA2 paired over dx with parity
// phase so every b-pair aliases an LDS.128 quad; DO NOT hoist/copy the loaded
// quads — it breaks the pack elision). TH=4 tile, 96 threads, occupancy 4,
// double-buffered TMA. New vs R8: KC=8 (24 chunks) and a split barrier so
// only warp 0 (the TMA issuer) waits at the refill fence.

#define MAXD 4
#define WIN  9
#define NDISP 81

#define BB 8
#define CC 192
#define HH 128
#define WW 128

#define TH 4            // tile rows per CTA
#define TW 32           // tile cols per CTA
#define KC 8            // channels per chunk (24 chunks)
#define NCHUNK (CC / KC)
#define NTHREADS 96     // 3 dy-groups (== warps) * (4 ty * 8 tx)

#define S2H (TH + 8)    // 12
#define S2W (TW + 8)    // 40
#define S1BYTES (KC * TH * TW * 4)       // 4096
#define S2BYTES (KC * S2H * S2W * 4)     // 15360
#define CHUNK_BYTES (S1BYTES + S2BYTES)  // 19456

// packed f32x2 ops
#define FMA2(d, a, b)      asm("fma.rn.f32x2 %0, %1, %2, %0;" : "+l"(d) : "l"(a), "l"(b))
#define PACK2(d, lo, hi)   asm("mov.b64 %0, {%1, %2};" : "=l"(d) : "f"(lo), "f"(hi))
#define UNPACK2(lo, hi, v) asm("mov.b64 {%0, %1}, %2;" : "=f"(lo), "=f"(hi) : "l"(v))

__device__ __forceinline__ unsigned smem_u32(const void* p) {
    unsigned a;
    asm("{ .reg .u64 t; cvta.to.shared.u64 t, %1; cvt.u32.u64 %0, t; }"
        : "=r"(a) : "l"(p));
    return a;
}
__device__ __forceinline__ void mbar_init(unsigned mbar, unsigned count) {
    asm volatile("mbarrier.init.shared.b64 [%0], %1;" :: "r"(mbar), "r"(count) : "memory");
}
__device__ __forceinline__ void mbar_expect_tx(unsigned mbar, unsigned bytes) {
    asm volatile("mbarrier.arrive.expect_tx.shared.b64 _, [%0], %1;"
                 :: "r"(mbar), "r"(bytes) : "memory");
}
__device__ __forceinline__ void mbar_wait(unsigned mbar, unsigned parity) {
    asm volatile(
        "{\n\t"
        ".reg .pred P;\n\t"
        "WAIT_LOOP_%=:\n\t"
        "mbarrier.try_wait.parity.acquire.cta.shared::cta.b64 P, [%0], %1, 0x989680;\n\t"
        "@P bra.uni WAIT_DONE_%=;\n\t"
        "bra.uni WAIT_LOOP_%=;\n\t"
        "WAIT_DONE_%=:\n\t"
        "}"
        :: "r"(mbar), "r"(parity) : "memory");
}
__device__ __forceinline__ void tma_load_3d(unsigned smem_dst, const void* tmap,
                                            int cx, int cy, int cz, unsigned mbar) {
    asm volatile(
        "cp.async.bulk.tensor.3d.shared::cta.global.tile.mbarrier::complete_tx::bytes "
        "[%0], [%1, {%2, %3, %4}], [%5];"
        :: "r"(smem_dst), "l"(tmap), "r"(cx), "r"(cy), "r"(cz), "r"(mbar)
        : "memory");
}
__device__ __forceinline__ void bar_arrive(int id, int cnt) {
    asm volatile("bar.arrive %0, %1;" :: "r"(id), "r"(cnt) : "memory");
}
__device__ __forceinline__ void bar_sync_named(int id, int cnt) {
    asm volatile("bar.sync %0, %1;" :: "r"(id), "r"(cnt) : "memory");
}

__global__ __launch_bounds__(NTHREADS, 4)
void corr_kernel(const __grid_constant__ CUtensorMap t1map,
                 const __grid_constant__ CUtensorMap t2map,
                 float* __restrict__ out)
{
    __shared__ __align__(128) float s1[2][KC][TH][TW];      // 8 KB
    __shared__ __align__(128) float s2[2][KC][S2H][S2W];    // 30 KB
    __shared__ __align__(8) unsigned long long mbar_full[2];

    const int tx0 = blockIdx.x * TW;
    const int ty0 = blockIdx.y * TH;
    const int b   = blockIdx.z;

    const int tid   = threadIdx.x;
    const int group = tid >> 5;        // warp id == dy group: dy in [3g, 3g+3)
    const int lane  = tid & 31;
    const int tx    = lane & 7;        // x-quad index
    const int ty    = lane >> 3;       // 0..3
    const int dyb   = group * 3;

    const unsigned mb0 = smem_u32(&mbar_full[0]);
    const unsigned mb1 = smem_u32(&mbar_full[1]);
    const unsigned s1a[2] = { smem_u32(&s1[0][0][0][0]), smem_u32(&s1[1][0][0][0]) };
    const unsigned s2a[2] = { smem_u32(&s2[0][0][0][0]), smem_u32(&s2[1][0][0][0]) };
    const int zbase = b * CC;

    if (tid == 0) { mbar_init(mb0, 1); mbar_init(mb1, 1); }
    __syncthreads();

    if (tid == 0) {
        mbar_expect_tx(mb0, CHUNK_BYTES);
        tma_load_3d(s1a[0], &t1map, tx0, ty0, zbase, mb0);
        tma_load_3d(s2a[0], &t2map, tx0 - MAXD, ty0 - MAXD, zbase, mb0);
        mbar_expect_tx(mb1, CHUNK_BYTES);
        tma_load_3d(s1a[1], &t1map, tx0, ty0, zbase + KC, mb1);
        tma_load_3d(s2a[1], &t2map, tx0 - MAXD, ty0 - MAXD, zbase + KC, mb1);
    }

    // accumulators: per (g, px): 4 dx-pairs (phase by px parity) + 1 scalar.
    // p even: pairs (0,1)(2,3)(4,5)(6,7), scalar dx=8
    // p odd : scalar dx=0, pairs (1,2)(3,4)(5,6)(7,8)
    unsigned long long acc2[3][4][4];   // 96 regs
    float accS[3][4];                   // 12 regs
    #pragma unroll
    for (int g = 0; g < 3; ++g)
        #pragma unroll
        for (int p = 0; p < 4; ++p) {
            accS[g][p] = 0.0f;
            #pragma unroll
            for (int j = 0; j < 4; ++j)
                acc2[g][p][j] = 0ull;
        }

    #pragma unroll 2
    for (int k = 0; k < NCHUNK; ++k) {
        const int buf = k & 1;
        const unsigned par = (unsigned)((k >> 1) & 1);
        mbar_wait(buf ? mb1 : mb0, par);

        // ---- compute chunk k from buf (R8 body: loads stay inline) ----
        #pragma unroll
        for (int kc = 0; kc < KC; ++kc) {
            float4 a4 = *(const float4*)&s1[buf][kc][ty][tx * 4];
            float af[4] = {a4.x, a4.y, a4.z, a4.w};
            unsigned long long aB[4];
            PACK2(aB[0], a4.x, a4.x);
            PACK2(aB[1], a4.y, a4.y);
            PACK2(aB[2], a4.z, a4.z);
            PACK2(aB[3], a4.w, a4.w);

            #pragma unroll
            for (int g = 0; g < 3; ++g) {
                const float* rowp = &s2[buf][kc][ty + dyb + g][tx * 4];
                float4 q0 = *(const float4*)(rowp);
                float4 q1 = *(const float4*)(rowp + 4);
                float4 q2 = *(const float4*)(rowp + 8);
                // even-aligned window pairs: sub-pairs of the quads (elided)
                unsigned long long e[6];
                PACK2(e[0], q0.x, q0.y); PACK2(e[1], q0.z, q0.w);
                PACK2(e[2], q1.x, q1.y); PACK2(e[3], q1.z, q1.w);
                PACK2(e[4], q2.x, q2.y); PACK2(e[5], q2.z, q2.w);
                float wf[12] = {q0.x, q0.y, q0.z, q0.w,
                                q1.x, q1.y, q1.z, q1.w,
                                q2.x, q2.y, q2.z, q2.w};

                #pragma unroll
                for (int p = 0; p < 4; ++p) {
                    const int off = (p + 1) >> 1;   // 0,1,1,2
                    #pragma unroll
                    for (int j = 0; j < 4; ++j)
                        FMA2(acc2[g][p][j], aB[p], e[off + j]);
                    const int sw = (p & 1) ? p : (p + 8);
                    accS[g][p] = fmaf(af[p], wf[sw], accS[g][p]);
                }
            }
        }

        // ---- refill fence: only warp 0 (TMA issuer) blocks ----
        if (k + 2 < NCHUNK) {
            const int barid = 1 + (k & 1);   // ping-pong ids: run-ahead safe
            if (group == 0) {
                bar_sync_named(barid, NTHREADS);
                if (lane == 0) {
                    const unsigned mb = buf ? mb1 : mb0;
                    mbar_expect_tx(mb, CHUNK_BYTES);
                    tma_load_3d(s1a[buf], &t1map, tx0, ty0,
                                zbase + (k + 2) * KC, mb);
                    tma_load_3d(s2a[buf], &t2map, tx0 - MAXD, ty0 - MAXD,
                                zbase + (k + 2) * KC, mb);
                }
            } else {
                bar_arrive(barid, NTHREADS);
            }
        }
    }

    // ---- epilogue: unpack dx-pairs, scale by 1/C, float4 stores ----
    const float scale = 1.0f / (float)CC;
    const int y  = ty0 + ty;
    const int x0 = tx0 + tx * 4;
    #pragma unroll
    for (int g = 0; g < 3; ++g) {
        float v[WIN][4];
        #pragma unroll
        for (int p = 0; p < 4; ++p) {
            if ((p & 1) == 0) {
                #pragma unroll
                for (int j = 0; j < 4; ++j)
                    UNPACK2(v[2 * j][p], v[2 * j + 1][p], acc2[g][p][j]);
                v[8][p] = accS[g][p];
            } else {
                v[0][p] = accS[g][p];
                #pragma unroll
                for (int j = 0; j < 4; ++j)
                    UNPACK2(v[2 * j + 1][p], v[2 * j + 2][p], acc2[g][p][j]);
            }
        }
        #pragma unroll
        for (int dx = 0; dx < WIN; ++dx) {
            int d = (dyb + g) * WIN + dx;
            *(float4*)&out[(((long)(b * NDISP) + d) * HH + y) * WW + x0] =
                make_float4(v[dx][0] * scale, v[dx][1] * scale,
                            v[dx][2] * scale, v[dx][3] * scale);
        }
    }
}

typedef CUresult (*EncodeFn)(CUtensorMap*, CUtensorMapDataType, cuuint32_t, void*,
                             const cuuint64_t*, const cuuint64_t*, const cuuint32_t*,
                             const cuuint32_t*, CUtensorMapInterleave, CUtensorMapSwizzle,
                             CUtensorMapL2promotion, CUtensorMapFloatOOBfill);

extern "C" void kernel_launch(void* const* d_in, const int* in_sizes, int n_in,
                              void* d_out, int out_size)
{
    float* in1 = (float*)d_in[0];
    float* in2 = (float*)d_in[1];
    float* out = (float*)d_out;

    EncodeFn encode = nullptr;
    cudaDriverEntryPointQueryResult qr;
    cudaGetDriverEntryPoint("cuTensorMapEncodeTiled", (void**)&encode,
                            cudaEnableDefault, &qr);

    CUtensorMap t1map, t2map;
    cuuint64_t dims[3]    = { WW, HH, (cuuint64_t)(BB * CC) };
    cuuint64_t strides[2] = { WW * 4ull, (cuuint64_t)HH * WW * 4ull };
    cuuint32_t elemstr[3] = { 1, 1, 1 };

    cuuint32_t box1[3] = { TW, TH, KC };
    encode(&t1map, CU_TENSOR_MAP_DATA_TYPE_FLOAT32, 3, in1,
           dims, strides, box1, elemstr,
           CU_TENSOR_MAP_INTERLEAVE_NONE, CU_TENSOR_MAP_SWIZZLE_NONE,
           CU_TENSOR_MAP_L2_PROMOTION_L2_128B, CU_TENSOR_MAP_FLOAT_OOB_FILL_NONE);

    cuuint32_t box2[3] = { S2W, S2H, KC };
    encode(&t2map, CU_TENSOR_MAP_DATA_TYPE_FLOAT32, 3, in2,
           dims, strides, box2, elemstr,
           CU_TENSOR_MAP_INTERLEAVE_NONE, CU_TENSOR_MAP_SWIZZLE_NONE,
           CU_TENSOR_MAP_L2_PROMOTION_L2_128B, CU_TENSOR_MAP_FLOAT_OOB_FILL_NONE);

    dim3 grid(WW / TW, HH / TH, BB);   // (4, 32, 8) = 1024 CTAs
    dim3 block(NTHREADS);
    corr_kernel<<<grid, block>>>(t1map, t2map, out);
}